// round 12
// baseline (speedup 1.0000x reference)
#include <cuda_runtime.h>

#define N_ITEMS 20000
#define ALPHA 0.2f
#define GRID 760               // 5 CTAs/SM x 152 SMs (persistent)
#define NGROUP (GRID * 2)      // independent row pipelines
#define S64 (NGROUP * 64)

#define BARG() asm volatile("bar.sync %0, 128;" :: "r"(barid) : "memory")

__global__ __launch_bounds__(256, 5) void gat_kernel(
    const float* __restrict__ item,
    const float* __restrict__ ent,
    const int*   __restrict__ adj,
    const float* __restrict__ W,
    const float* __restrict__ a,
    float*       __restrict__ out)
{
    __shared__ float wa1s[64], wa2s[64];
    __shared__ float dbuf[2][64];
    __shared__ float xbuf[2][64];
    __shared__ float part[2][256];
    __shared__ float smsum[2][2][2];   // [group][row parity][warp 0/1]
    __shared__ float s1buf[2];

    const int t    = threadIdx.x;
    const int gi   = t >> 7;
    const int gt   = t & 127;
    const int lane = t & 31;
    const int wg   = gt >> 5;
    const int mB   = gt >> 4;          // 0..7
    const int fs   = gt & 15;
    const int fe   = gt - 64;          // epilogue f (wg>=2)
    const int barid = 1 + gi;

    // --- wa1 = W@a1, wa2 = W@a2 (once per CTA) ---
    {
        const int f = t >> 2, q = t & 3;
        const float* wr = W + f * 64 + q * 16;
        float p1 = 0.f, p2 = 0.f;
#pragma unroll
        for (int i = 0; i < 4; ++i) {
            float4 wv = *(const float4*)(wr + i * 4);
            float4 y1 = *(const float4*)(a + q * 16 + i * 4);
            float4 y2 = *(const float4*)(a + 64 + q * 16 + i * 4);
            p1 += wv.x*y1.x + wv.y*y1.y + wv.z*y1.z + wv.w*y1.w;
            p2 += wv.x*y2.x + wv.y*y2.y + wv.z*y2.z + wv.w*y2.w;
        }
        p1 += __shfl_xor_sync(~0u, p1, 1); p1 += __shfl_xor_sync(~0u, p1, 2);
        p2 += __shfl_xor_sync(~0u, p2, 1); p2 += __shfl_xor_sync(~0u, p2, 2);
        if (q == 0) { wa1s[f] = p1; wa2s[f] = p2; }
    }
    __syncthreads();
    const float4 w2 = *(const float4*)&wa2s[fs * 4];

    int n   = blockIdx.x * 2 + gi;
    int off = n * 64;

    // --- Prime row n: masks + tile; masks for n+1 balloted immediately ---
    unsigned bm0, bm1, nx0 = 0, nx1 = 0;
    {
        const int a0 = adj[off + lane], a1 = adj[off + 32 + lane];
        bm0 = __ballot_sync(~0u, a0 > 0);
        bm1 = __ballot_sync(~0u, a1 > 0);
    }
    float4 v[8];
    {
        const float* eb = ent + (size_t)off * 64;
#pragma unroll
        for (int c = 0; c < 8; ++c) {
            const int m = mB + 8 * c;
            const bool lv = (m < 32) ? ((bm0 >> m) & 1u) : ((bm1 >> (m - 32)) & 1u);
            v[c] = lv ? *(const float4*)(eb + (size_t)(gt + 128 * c) * 4)
                      : make_float4(0.f, 0.f, 0.f, 0.f);
        }
    }
    bool hasN = (n + NGROUP) < N_ITEMS;
    if (hasN) {
        const int a0 = adj[off + S64 + lane], a1 = adj[off + S64 + 32 + lane];
        nx0 = __ballot_sync(~0u, a0 > 0);
        nx1 = __ballot_sync(~0u, a1 > 0);
    }
    float ia = 0.f, ib = 0.f, iePrev = 0.f, ieCur = 0.f;
    if (wg == 2) { ia = item[off + lane]; ib = item[off + 32 + lane]; }
    if (wg >= 2) { ieCur = item[off + fe]; }

    int par = 0, offPrev = -1;

    while (true) {
        // ---- window A: d-phase (all warps) + s1 (warp 2) ----
        float dd[8];
#pragma unroll
        for (int c = 0; c < 8; ++c)
            dd[c] = v[c].x*w2.x + v[c].y*w2.y + v[c].z*w2.z + v[c].w*w2.w;
        float e0 = ((lane&1)? dd[1]:dd[0]) + __shfl_xor_sync(~0u, (lane&1)? dd[0]:dd[1], 1);
        float e1 = ((lane&1)? dd[3]:dd[2]) + __shfl_xor_sync(~0u, (lane&1)? dd[2]:dd[3], 1);
        float e2 = ((lane&1)? dd[5]:dd[4]) + __shfl_xor_sync(~0u, (lane&1)? dd[4]:dd[5], 1);
        float e3 = ((lane&1)? dd[7]:dd[6]) + __shfl_xor_sync(~0u, (lane&1)? dd[6]:dd[7], 1);
        float f0 = ((lane&2)? e1:e0) + __shfl_xor_sync(~0u, (lane&2)? e0:e1, 2);
        float f1 = ((lane&2)? e3:e2) + __shfl_xor_sync(~0u, (lane&2)? e2:e3, 2);
        float g0 = ((lane&4)? f1:f0) + __shfl_xor_sync(~0u, (lane&4)? f0:f1, 4);
        g0 += __shfl_xor_sync(~0u, g0, 8);
        if (!(lane & 8)) dbuf[gi][mB + 8 * (lane & 7)] = g0;
        if (wg == 2) {
            float p = ia * wa1s[lane] + ib * wa1s[32 + lane];
            p += __shfl_xor_sync(~0u, p, 16);
            p += __shfl_xor_sync(~0u, p, 8);
            p += __shfl_xor_sync(~0u, p, 4);
            p += __shfl_xor_sync(~0u, p, 2);
            p += __shfl_xor_sync(~0u, p, 1);
            if (lane == 0) s1buf[gi] = p;
        }
        BARG();

        // ---- window B: wg0-1: x + sum; wg2-3: prev epilogue + item prefetch ----
        if (wg < 2) {
            float e = s1buf[gi] + dbuf[gi][gt];
            e = fmaxf(e, ALPHA * e);
            const unsigned mk = wg ? bm1 : bm0;
            const float x = ((mk >> lane) & 1u) ? __expf(e) : 0.f;
            xbuf[gi][gt] = x;
            float sm = x;
            sm += __shfl_xor_sync(~0u, sm, 16);
            sm += __shfl_xor_sync(~0u, sm, 8);
            sm += __shfl_xor_sync(~0u, sm, 4);
            sm += __shfl_xor_sync(~0u, sm, 2);
            sm += __shfl_xor_sync(~0u, sm, 1);
            if (lane == 0) smsum[gi][par][wg] = sm;
        } else {
            if (offPrev >= 0) {
                const float r = (part[gi][fe] + part[gi][64 + fe])
                              + (part[gi][128 + fe] + part[gi][192 + fe]);
                const float inv = 1.0f / (smsum[gi][par ^ 1][0] + smsum[gi][par ^ 1][1]);
                out[offPrev + fe] = r * inv + iePrev;
            }
            iePrev = ieCur;
            if (hasN) {
                ieCur = item[off + S64 + fe];
                if (wg == 2) { ia = item[off + S64 + lane]; ib = item[off + S64 + 32 + lane]; }
            }
        }
        BARG();

        // ---- window C: acc(current) interleaved with next-row tile loads ----
        const bool hasNN = (n + 2 * NGROUP) < N_ITEMS;
        {
            const float* ebN = ent + (size_t)(off + S64) * 64;
            float4 acc = make_float4(0.f, 0.f, 0.f, 0.f);
#pragma unroll
            for (int c = 0; c < 8; ++c) {
                const float xv = xbuf[gi][mB + 8 * c];
                acc.x = fmaf(xv, v[c].x, acc.x);
                acc.y = fmaf(xv, v[c].y, acc.y);
                acc.z = fmaf(xv, v[c].z, acc.z);
                acc.w = fmaf(xv, v[c].w, acc.w);
                const int m = mB + 8 * c;
                const bool lv = hasN && ((m < 32) ? ((nx0 >> m) & 1u)
                                                  : ((nx1 >> (m - 32)) & 1u));
                v[c] = lv ? *(const float4*)(ebN + (size_t)(gt + 128 * c) * 4)
                          : make_float4(0.f, 0.f, 0.f, 0.f);
            }
            acc.x += __shfl_xor_sync(~0u, acc.x, 16);
            acc.y += __shfl_xor_sync(~0u, acc.y, 16);
            acc.z += __shfl_xor_sync(~0u, acc.z, 16);
            acc.w += __shfl_xor_sync(~0u, acc.w, 16);
            if (lane < 16) *(float4*)&part[gi][wg * 64 + lane * 4] = acc;
        }
        // masks rotate; adj for n+2 loaded and balloted immediately (jn dies here)
        bm0 = nx0; bm1 = nx1;
        if (hasNN) {
            const int a0 = adj[off + 2 * S64 + lane];
            const int a1 = adj[off + 2 * S64 + 32 + lane];
            nx0 = __ballot_sync(~0u, a0 > 0);
            nx1 = __ballot_sync(~0u, a1 > 0);
        } else { nx0 = 0; nx1 = 0; }

        offPrev = off; off += S64; n += NGROUP; par ^= 1; hasN = hasNN;
        if (n >= N_ITEMS) break;
    }

    // ---- drain: epilogue for the final row ----
    BARG();
    if (wg >= 2) {
        const float r = (part[gi][fe] + part[gi][64 + fe])
                      + (part[gi][128 + fe] + part[gi][192 + fe]);
        const float inv = 1.0f / (smsum[gi][par ^ 1][0] + smsum[gi][par ^ 1][1]);
        out[offPrev + fe] = r * inv + iePrev;
    }
}

extern "C" void kernel_launch(void* const* d_in, const int* in_sizes, int n_in,
                              void* d_out, int out_size) {
    const float* item = (const float*)d_in[0];
    const float* ent  = (const float*)d_in[1];
    const int*   adj  = (const int*)d_in[2];
    const float* W    = (const float*)d_in[3];
    const float* a    = (const float*)d_in[4];
    float* out = (float*)d_out;

    gat_kernel<<<GRID, 256>>>(item, ent, adj, W, a, out);
}

// round 13
// speedup vs baseline: 1.9098x; 1.9098x over previous
#include <cuda_runtime.h>

#define N_ITEMS 20000
#define ALPHA 0.2f
#define GRID 608               // 4 CTAs/SM x 152 SMs (persistent)
#define NGROUP (GRID * 2)      // 1216 independent row pipelines
#define S64 (NGROUP * 64)

#define BARG() asm volatile("bar.sync %0, 128;" :: "r"(barid) : "memory")

__global__ __launch_bounds__(256, 4) void gat_kernel(
    const float* __restrict__ item,
    const float* __restrict__ ent,
    const int*   __restrict__ adj,
    const float* __restrict__ W,
    const float* __restrict__ a,
    float*       __restrict__ out)
{
    __shared__ float wa1s[64], wa2s[64];
    __shared__ float xbuf[2][64];       // unnormalized att, indexed by m
    __shared__ float part[2][512];      // 8 half-warp output partials x 64 f
    __shared__ float smsum[2][2][4];    // [group][parity][warp]
    __shared__ float s1buf[2][2];       // [group][parity]

    const int t    = threadIdx.x;
    const int gi   = t >> 7;
    const int gt   = t & 127;
    const int lane = t & 31;
    const int wg   = gt >> 5;
    const int mB   = gt >> 4;              // 2*wg + (lane>>4), 0..7
    const int fs   = lane & 15;            // f-chunk (float4 id)
    const int fe   = gt - 64;              // epilogue f (wg>=2)
    const int barid = 1 + gi;
    const int mrow = mB + 8 * (lane & 7);  // row whose d this lane owns post-butterfly

    // --- wa1 = W@a1, wa2 = W@a2 (once per CTA) ---
    {
        const int f = t >> 2, q = t & 3;
        const float* wr = W + f * 64 + q * 16;
        float p1 = 0.f, p2 = 0.f;
#pragma unroll
        for (int i = 0; i < 4; ++i) {
            float4 wv = *(const float4*)(wr + i * 4);
            float4 y1 = *(const float4*)(a + q * 16 + i * 4);
            float4 y2 = *(const float4*)(a + 64 + q * 16 + i * 4);
            p1 += wv.x*y1.x + wv.y*y1.y + wv.z*y1.z + wv.w*y1.w;
            p2 += wv.x*y2.x + wv.y*y2.y + wv.z*y2.z + wv.w*y2.w;
        }
        p1 += __shfl_xor_sync(~0u, p1, 1); p1 += __shfl_xor_sync(~0u, p1, 2);
        p2 += __shfl_xor_sync(~0u, p2, 1); p2 += __shfl_xor_sync(~0u, p2, 2);
        if (q == 0) { wa1s[f] = p1; wa2s[f] = p2; }
    }
    __syncthreads();
    const float4 w2   = *(const float4*)&wa2s[fs * 4];
    const float  wa1a = wa1s[lane];
    const float  wa1b = wa1s[32 + lane];

    int n   = blockIdx.x * 2 + gi;
    int off = n * 64;

    // --- Prime row n: masks + tile; masks for n+1 ---
    unsigned bm0, bm1, nx0 = 0, nx1 = 0;
    {
        const int a0 = adj[off + lane], a1 = adj[off + 32 + lane];
        bm0 = __ballot_sync(~0u, a0 > 0);
        bm1 = __ballot_sync(~0u, a1 > 0);
    }
    float4 v[8];
    {
        const float* eb = ent + (size_t)off * 64;
#pragma unroll
        for (int c = 0; c < 8; ++c) {
            const int m = mB + 8 * c;
            const bool lv = (m < 32) ? ((bm0 >> m) & 1u) : ((bm1 >> (m - 32)) & 1u);
            v[c] = lv ? *(const float4*)(eb + (size_t)(gt + 128 * c) * 4)
                      : make_float4(0.f, 0.f, 0.f, 0.f);
        }
    }
    bool hasN = (n + NGROUP) < N_ITEMS;
    if (hasN) {
        const int a0 = adj[off + S64 + lane], a1 = adj[off + S64 + 32 + lane];
        nx0 = __ballot_sync(~0u, a0 > 0);
        nx1 = __ballot_sync(~0u, a1 > 0);
    }
    float ia = 0.f, ib = 0.f, iePrev = 0.f, ieCur = 0.f;
    if (wg == 2) {
        ia = item[off + lane]; ib = item[off + 32 + lane];
        float p = ia * wa1a + ib * wa1b;
        p += __shfl_xor_sync(~0u, p, 16);
        p += __shfl_xor_sync(~0u, p, 8);
        p += __shfl_xor_sync(~0u, p, 4);
        p += __shfl_xor_sync(~0u, p, 2);
        p += __shfl_xor_sync(~0u, p, 1);
        if (lane == 0) s1buf[gi][0] = p;
        if (hasN) { ia = item[off + S64 + lane]; ib = item[off + S64 + 32 + lane]; }
    }
    if (wg >= 2) ieCur = item[off + fe];

    int par = 0, offPrev = -1;
    BARG();   // s1buf[0] visible

    while (true) {
        // ==== Window M: d-butterfly -> x (own 16 rows, in-warp) + side jobs ====
        float dd[8];
#pragma unroll
        for (int c = 0; c < 8; ++c)
            dd[c] = v[c].x*w2.x + v[c].y*w2.y + v[c].z*w2.z + v[c].w*w2.w;
        float e0 = ((lane&1)? dd[1]:dd[0]) + __shfl_xor_sync(~0u, (lane&1)? dd[0]:dd[1], 1);
        float e1 = ((lane&1)? dd[3]:dd[2]) + __shfl_xor_sync(~0u, (lane&1)? dd[2]:dd[3], 1);
        float e2 = ((lane&1)? dd[5]:dd[4]) + __shfl_xor_sync(~0u, (lane&1)? dd[4]:dd[5], 1);
        float e3 = ((lane&1)? dd[7]:dd[6]) + __shfl_xor_sync(~0u, (lane&1)? dd[6]:dd[7], 1);
        float f0 = ((lane&2)? e1:e0) + __shfl_xor_sync(~0u, (lane&2)? e0:e1, 2);
        float f1 = ((lane&2)? e3:e2) + __shfl_xor_sync(~0u, (lane&2)? e2:e3, 2);
        float g0 = ((lane&4)? f1:f0) + __shfl_xor_sync(~0u, (lane&4)? f0:f1, 4);
        g0 += __shfl_xor_sync(~0u, g0, 8);

        float e = s1buf[gi][par] + g0;
        e = fmaxf(e, ALPHA * e);
        const unsigned mbit = (mrow < 32) ? ((bm0 >> mrow) & 1u) : ((bm1 >> (mrow - 32)) & 1u);
        const float x = mbit ? __expf(e) : 0.f;
        if (!(lane & 8)) xbuf[gi][mrow] = x;
        float xs = (lane & 8) ? 0.f : x;           // dedupe duplicate holders
        xs += __shfl_xor_sync(~0u, xs, 1);
        xs += __shfl_xor_sync(~0u, xs, 2);
        xs += __shfl_xor_sync(~0u, xs, 4);
        xs += __shfl_xor_sync(~0u, xs, 16);
        if (lane == 0) smsum[gi][par][wg] = xs;

        if (wg == 2) {   // s1 for NEXT row, one ahead
            if (hasN) {
                float p = ia * wa1a + ib * wa1b;
                p += __shfl_xor_sync(~0u, p, 16);
                p += __shfl_xor_sync(~0u, p, 8);
                p += __shfl_xor_sync(~0u, p, 4);
                p += __shfl_xor_sync(~0u, p, 2);
                p += __shfl_xor_sync(~0u, p, 1);
                if (lane == 0) s1buf[gi][par ^ 1] = p;
                if ((n + 2 * NGROUP) < N_ITEMS) {
                    ia = item[off + 2 * S64 + lane];
                    ib = item[off + 2 * S64 + 32 + lane];
                }
            }
        }
        if (wg >= 2) {   // epilogue for previous row
            if (offPrev >= 0) {
                const int pp = par ^ 1;
                const float r = ((part[gi][fe]        + part[gi][64 + fe])
                              +  (part[gi][128 + fe]  + part[gi][192 + fe]))
                              + ((part[gi][256 + fe]  + part[gi][320 + fe])
                              +  (part[gi][384 + fe]  + part[gi][448 + fe]));
                const float inv = 1.0f / ((smsum[gi][pp][0] + smsum[gi][pp][1])
                                        + (smsum[gi][pp][2] + smsum[gi][pp][3]));
                out[offPrev + fe] = r * inv + iePrev;
            }
            iePrev = ieCur;
            if (hasN) ieCur = item[off + S64 + fe];
        }
        BARG();

        // ==== Window C: acc(current, x from xbuf) + next-row tile LDGs ====
        const bool hasNN = (n + 2 * NGROUP) < N_ITEMS;
        {
            const float* ebN = ent + (size_t)(off + S64) * 64;
            float4 acc = make_float4(0.f, 0.f, 0.f, 0.f);
#pragma unroll
            for (int c = 0; c < 8; ++c) {
                const float xv = xbuf[gi][mB + 8 * c];
                acc.x = fmaf(xv, v[c].x, acc.x);
                acc.y = fmaf(xv, v[c].y, acc.y);
                acc.z = fmaf(xv, v[c].z, acc.z);
                acc.w = fmaf(xv, v[c].w, acc.w);
                const int m = mB + 8 * c;
                const bool lv = hasN && ((m < 32) ? ((nx0 >> m) & 1u)
                                                  : ((nx1 >> (m - 32)) & 1u));
                v[c] = lv ? *(const float4*)(ebN + (size_t)(gt + 128 * c) * 4)
                          : make_float4(0.f, 0.f, 0.f, 0.f);
            }
            // store both m-halves; epilogue sums 8 (no shfl16 chain)
            *(float4*)&part[gi][mB * 64 + fs * 4] = acc;
        }
        bm0 = nx0; bm1 = nx1;
        if (hasNN) {
            const int a0 = adj[off + 2 * S64 + lane];
            const int a1 = adj[off + 2 * S64 + 32 + lane];
            nx0 = __ballot_sync(~0u, a0 > 0);
            nx1 = __ballot_sync(~0u, a1 > 0);
        } else { nx0 = 0; nx1 = 0; }

        offPrev = off; off += S64; n += NGROUP; par ^= 1; hasN = hasNN;
        BARG();
        if (n >= N_ITEMS) break;
    }

    // ---- drain: epilogue for the final row ----
    if (wg >= 2) {
        const int pp = par ^ 1;
        const float r = ((part[gi][fe]        + part[gi][64 + fe])
                      +  (part[gi][128 + fe]  + part[gi][192 + fe]))
                      + ((part[gi][256 + fe]  + part[gi][320 + fe])
                      +  (part[gi][384 + fe]  + part[gi][448 + fe]));
        const float inv = 1.0f / ((smsum[gi][pp][0] + smsum[gi][pp][1])
                                + (smsum[gi][pp][2] + smsum[gi][pp][3]));
        out[offPrev + fe] = r * inv + iePrev;
    }
}

extern "C" void kernel_launch(void* const* d_in, const int* in_sizes, int n_in,
                              void* d_out, int out_size) {
    const float* item = (const float*)d_in[0];
    const float* ent  = (const float*)d_in[1];
    const int*   adj  = (const int*)d_in[2];
    const float* W    = (const float*)d_in[3];
    const float* a    = (const float*)d_in[4];
    float* out = (float*)d_out;

    gat_kernel<<<GRID, 256>>>(item, ent, adj, W, a, out);
}